// round 16
// baseline (speedup 1.0000x reference)
#include <cuda_runtime.h>
#include <math.h>

#define NN 50000
#define NE 800000

// ---------------- scratch (no allocations allowed) ----------------
__device__ float g_f[NN * 64];
__device__ float g_x[NN * 64];
__device__ float g_el[NN * 4];
__device__ float g_er[NN * 4];
__device__ float g_elmax[8];     // [2 bufs][4 heads]
__device__ int   g_srcs[NE];
__device__ int   g_deg[NN];
__device__ int   g_rowptr[NN + 1];
__device__ int   g_cursor[NN];

__device__ __forceinline__ float lrelu(float v) { return v > 0.f ? v : 0.2f * v; }

__device__ __forceinline__ float sel4(float4 q, int h) {
    float a = (h == 0) ? q.x : q.y;
    float b = (h == 2) ? q.z : q.w;
    return (h < 2) ? a : b;
}

// float atomic max via int-max (v>=0) / uint-min (v<0); identity init = 0xFFFFFFFF
__device__ __forceinline__ void atomicMaxF(float* addr, float v) {
    if (v >= 0.f) atomicMax((int*)addr, __float_as_int(v));
    else          atomicMin((unsigned int*)addr, __float_as_uint(v));
}

// ---- packed fp32x2 helpers (sm_10x FFMA2) ----
__device__ __forceinline__ unsigned long long pack2(float x, float y) {
    unsigned long long r;
    asm("mov.b64 %0, {%1, %2};" : "=l"(r) : "f"(x), "f"(y));
    return r;
}
__device__ __forceinline__ void unpack2(unsigned long long v, float& x, float& y) {
    asm("mov.b64 {%0, %1}, %2;" : "=f"(x), "=f"(y) : "l"(v));
}
__device__ __forceinline__ void ffma2(unsigned long long& d,
                                      unsigned long long a,
                                      unsigned long long b) {
    asm("fma.rn.f32x2 %0, %1, %2, %0;" : "+l"(d) : "l"(a), "l"(b));
}

// ---------------- GEMM body (256 threads, BM=128 BN=64 BK=32, 4x8/thread) ----------------
template <int K, int H>
__device__ __forceinline__ void linear_body(int bid,
                                            const float* __restrict__ x,
                                            const float* __restrict__ W,
                                            const float* __restrict__ al,
                                            const float* __restrict__ ar,
                                            float* __restrict__ f,
                                            float* __restrict__ el,
                                            float* __restrict__ er,
                                            float* __restrict__ elmax,
                                            int N) {
    __shared__ float xs[32][132];
    __shared__ float Ws[32][64];
    __shared__ float smax[4];
    const int tid = threadIdx.x;     // 0..255
    const int tx = tid & 7;          // col group -> c0 = tx*8
    const int ty = tid >> 3;         // 0..31    -> r0 = ty*4
    const int rb = bid * 128;
    const int c0 = tx * 8;
    const int r0 = ty * 4;

    if (tid < 4) smax[tid] = __uint_as_float(0xFFFFFFFFu);

    unsigned long long accp[4][4];
    #pragma unroll
    for (int i = 0; i < 4; i++)
        #pragma unroll
        for (int j = 0; j < 4; j++) accp[i][j] = 0ull;

    const int kk = tid & 31;
    const int rr = tid >> 5;   // 0..7

    for (int kb = 0; kb < K; kb += 32) {
        #pragma unroll
        for (int r = 0; r < 128; r += 8) {
            int row = rb + r + rr;
            xs[kk][r + rr] = (row < N) ? x[row * K + kb + kk] : 0.f;
        }
        #pragma unroll
        for (int i = 0; i < 8; i++) {
            int idx = tid + i * 256;
            int k = idx >> 6, c = idx & 63;
            Ws[k][c] = W[(kb + k) * 64 + c];
        }
        __syncthreads();

        #pragma unroll
        for (int k = 0; k < 32; k++) {
            unsigned long long xv2[4], wv2[4];
            #pragma unroll
            for (int i = 0; i < 4; i++) {
                float xv = xs[k][r0 + i];
                xv2[i] = pack2(xv, xv);
            }
            #pragma unroll
            for (int j = 0; j < 4; j++)
                wv2[j] = *(const unsigned long long*)&Ws[k][c0 + 2 * j];
            #pragma unroll
            for (int i = 0; i < 4; i++)
                #pragma unroll
                for (int j = 0; j < 4; j++)
                    ffma2(accp[i][j], xv2[i], wv2[j]);
        }
        __syncthreads();
    }

    float acc[4][8];
    #pragma unroll
    for (int i = 0; i < 4; i++)
        #pragma unroll
        for (int j = 0; j < 4; j++)
            unpack2(accp[i][j], acc[i][2 * j], acc[i][2 * j + 1]);

    #pragma unroll
    for (int i = 0; i < 4; i++) {
        int row = rb + r0 + i;
        if (row < N) {
            float4 a = make_float4(acc[i][0], acc[i][1], acc[i][2], acc[i][3]);
            float4 b = make_float4(acc[i][4], acc[i][5], acc[i][6], acc[i][7]);
            float4* p = (float4*)(f + row * 64 + c0);
            p[0] = a;
            p[1] = b;
        }
    }

    // fused scores epilogue
    float al_c[8], ar_c[8];
    #pragma unroll
    for (int j = 0; j < 8; j++) { al_c[j] = al[c0 + j]; ar_c[j] = ar[c0 + j]; }

    float localmax = -1e30f;
    bool wrote = false;
    #pragma unroll
    for (int i = 0; i < 4; i++) {
        float pl = 0.f, pr = 0.f;
        #pragma unroll
        for (int j = 0; j < 8; j++) {
            pl = fmaf(acc[i][j], al_c[j], pl);
            pr = fmaf(acc[i][j], ar_c[j], pr);
        }
        int row = rb + r0 + i;
        if (H == 4) {
            pl += __shfl_xor_sync(0xffffffffu, pl, 1);
            pr += __shfl_xor_sync(0xffffffffu, pr, 1);
            if ((tx & 1) == 0 && row < N) {
                int head = tx >> 1;
                el[row * 4 + head] = pl;
                er[row * 4 + head] = pr;
                localmax = fmaxf(localmax, pl);
                wrote = true;
            }
        } else {
            #pragma unroll
            for (int o = 1; o < 8; o <<= 1) {
                pl += __shfl_xor_sync(0xffffffffu, pl, o);
                pr += __shfl_xor_sync(0xffffffffu, pr, o);
            }
            if (tx == 0 && row < N) {
                el[row] = pl;
                er[row] = pr;
                localmax = fmaxf(localmax, pl);
                wrote = true;
            }
        }
    }
    __syncthreads();
    if (wrote) {
        int head = (H == 4) ? (tx >> 1) : 0;
        atomicMaxF(&smax[head], localmax);
    }
    __syncthreads();
    if (tid < H) atomicMaxF(&elmax[tid], smax[tid]);
}

// plain linear launch (layers 1, 2)
template <int K, int H>
__global__ void linear_kernel(const float* __restrict__ x, const float* __restrict__ W,
                              const float* __restrict__ al, const float* __restrict__ ar,
                              float* __restrict__ f, float* __restrict__ el,
                              float* __restrict__ er, float* __restrict__ elmax, int N) {
    linear_body<K, H>(blockIdx.x, x, W, al, ar, f, el, er, elmax, N);
}

// fused layer-0 linear + degree histogram (independent work, one launch)
template <int K, int H>
__global__ void linear_hist_kernel(const float* __restrict__ x, const float* __restrict__ W,
                                   const float* __restrict__ al, const float* __restrict__ ar,
                                   float* __restrict__ f, float* __restrict__ el,
                                   float* __restrict__ er, float* __restrict__ elmax,
                                   int N, int linBlocks,
                                   const int* __restrict__ dst, int* __restrict__ deg, int E) {
    if ((int)blockIdx.x < linBlocks) {
        linear_body<K, H>(blockIdx.x, x, W, al, ar, f, el, er, elmax, N);
    } else {
        int t = (blockIdx.x - linBlocks) * blockDim.x + threadIdx.x;
        int e = t * 4;
        if (e + 4 <= E) {
            int4 d = __ldg((const int4*)(dst + e));
            atomicAdd(&deg[d.x], 1);
            atomicAdd(&deg[d.y], 1);
            atomicAdd(&deg[d.z], 1);
            atomicAdd(&deg[d.w], 1);
        } else {
            for (; e < E; e++) atomicAdd(&deg[dst[e]], 1);
        }
    }
}

// ---------------- CSR scan + scatter ----------------

__global__ void scan_kernel(const int* __restrict__ deg, int* __restrict__ rowptr,
                            int* __restrict__ cursor, int n) {
    __shared__ int wsum[32];
    const int tid = threadIdx.x;
    const int lane = tid & 31;
    const int wid = tid >> 5;
    const int CH = (n + 1023) / 1024;
    int beg = tid * CH;
    int end = beg + CH; if (end > n) end = n; if (beg > n) beg = n;
    int sum = 0;
    for (int i = beg; i < end; i++) sum += deg[i];

    int v = sum;
    #pragma unroll
    for (int o = 1; o < 32; o <<= 1) {
        int u = __shfl_up_sync(0xffffffffu, v, o);
        if (lane >= o) v += u;
    }
    if (lane == 31) wsum[wid] = v;
    __syncthreads();
    if (wid == 0) {
        int w = wsum[lane];
        #pragma unroll
        for (int o = 1; o < 32; o <<= 1) {
            int u = __shfl_up_sync(0xffffffffu, w, o);
            if (lane >= o) w += u;
        }
        wsum[lane] = w;
    }
    __syncthreads();

    int run = v - sum + (wid > 0 ? wsum[wid - 1] : 0);
    for (int i = beg; i < end; i++) {
        rowptr[i] = run;
        cursor[i] = run;
        run += deg[i];
    }
    if (tid == 1023) rowptr[n] = run;
}

__global__ void scatter_kernel(const int* __restrict__ src, const int* __restrict__ dst,
                               int* __restrict__ cursor, int* __restrict__ srcs, int E) {
    int t = blockIdx.x * blockDim.x + threadIdx.x;
    int e = t * 4;
    if (e + 4 <= E) {
        int4 s = __ldg((const int4*)(src + e));
        int4 d = __ldg((const int4*)(dst + e));
        int p0 = atomicAdd(&cursor[d.x], 1);
        int p1 = atomicAdd(&cursor[d.y], 1);
        int p2 = atomicAdd(&cursor[d.z], 1);
        int p3 = atomicAdd(&cursor[d.w], 1);
        srcs[p0] = s.x; srcs[p1] = s.y; srcs[p2] = s.z; srcs[p3] = s.w;
    } else {
        for (; e < E; e++) {
            int pos = atomicAdd(&cursor[dst[e]], 1);
            srcs[pos] = src[e];
        }
    }
}

// ---------------- fused single-pass softmax+aggregation ----------------
// 2 nodes per warp; each lane owns 4 feature dims (float4).
template <int H>
__global__ void gat_node_kernel(const int* __restrict__ rowptr,
                                const int* __restrict__ srcs,
                                const float* __restrict__ f,
                                const float* __restrict__ el,
                                const float* __restrict__ er,
                                const float* __restrict__ elmax,
                                const float* __restrict__ b,
                                float* __restrict__ out,
                                int N, int do_elu,
                                float* __restrict__ reset_ptr) {
    if (reset_ptr && blockIdx.x == 0 && threadIdx.x < 4)
        reset_ptr[threadIdx.x] = __uint_as_float(0xFFFFFFFFu);

    int t = blockIdx.x * blockDim.x + threadIdx.x;
    int warp = t >> 5;
    int lane = t & 31;
    int half = lane >> 4;
    int hl = lane & 15;
    int node = warp * 2 + half;
    if (node >= N) return;
    const int beg = rowptr[node], end = rowptr[node + 1];

    const int hh = (H == 4) ? (hl >> 2) : 0;
    float er_h, B;
    if (H == 4) {
        float4 er4 = __ldg((const float4*)er + node);
        float4 em4 = __ldg((const float4*)elmax);
        er_h = sel4(er4, hh);
        B = lrelu(sel4(em4, hh) + er_h);
    } else {
        er_h = __ldg(er + node);
        B = lrelu(__ldg(elmax) + er_h);
    }

    float ax = 0.f, ay = 0.f, az = 0.f, aw = 0.f, sw = 0.f;
    const float4* f4 = (const float4*)f;
    const float4* el4 = (const float4*)el;

    int i = beg;
    for (; i + 4 <= end; i += 4) {
        int s[4];
        #pragma unroll
        for (int u = 0; u < 4; u++) s[u] = __ldg(srcs + i + u);
        float e[4]; float4 v[4];
        #pragma unroll
        for (int u = 0; u < 4; u++) {
            e[u] = (H == 4) ? sel4(__ldg(el4 + s[u]), hh) : __ldg(el + s[u]);
            v[u] = __ldg(f4 + s[u] * 16 + hl);
        }
        #pragma unroll
        for (int u = 0; u < 4; u++) {
            float w = __expf(lrelu(e[u] + er_h) - B);
            sw += w;
            ax = fmaf(w, v[u].x, ax);
            ay = fmaf(w, v[u].y, ay);
            az = fmaf(w, v[u].z, az);
            aw = fmaf(w, v[u].w, aw);
        }
    }
    for (; i < end; i++) {
        int s0 = __ldg(srcs + i);
        float e0 = (H == 4) ? sel4(__ldg(el4 + s0), hh) : __ldg(el + s0);
        float4 v0 = __ldg(f4 + s0 * 16 + hl);
        float w0 = __expf(lrelu(e0 + er_h) - B);
        sw += w0;
        ax = fmaf(w0, v0.x, ax);
        ay = fmaf(w0, v0.y, ay);
        az = fmaf(w0, v0.z, az);
        aw = fmaf(w0, v0.w, aw);
    }

    float inv = (sw > 0.f) ? 1.f / sw : 0.f;
    float4 bb = __ldg((const float4*)b + hl);
    ax = ax * inv + bb.x;
    ay = ay * inv + bb.y;
    az = az * inv + bb.z;
    aw = aw * inv + bb.w;
    if (do_elu) {
        ax = ax > 0.f ? ax : expm1f(ax);
        ay = ay > 0.f ? ay : expm1f(ay);
        az = az > 0.f ? az : expm1f(az);
        aw = aw > 0.f ? aw : expm1f(aw);
    }
    float4 r; r.x = ax; r.y = ay; r.z = az; r.w = aw;
    ((float4*)out)[node * 16 + hl] = r;
}

// ---------------- host ----------------

extern "C" void kernel_launch(void* const* d_in, const int* in_sizes, int n_in,
                              void* d_out, int out_size) {
    const float* h   = (const float*)d_in[0];
    const int*   src = (const int*)d_in[1];
    const int*   dst = (const int*)d_in[2];
    const float* W0  = (const float*)d_in[3];
    const float* al0 = (const float*)d_in[4];
    const float* ar0 = (const float*)d_in[5];
    const float* b0  = (const float*)d_in[6];
    const float* W1  = (const float*)d_in[7];
    const float* al1 = (const float*)d_in[8];
    const float* ar1 = (const float*)d_in[9];
    const float* b1  = (const float*)d_in[10];
    const float* W2  = (const float*)d_in[11];
    const float* al2 = (const float*)d_in[12];
    const float* ar2 = (const float*)d_in[13];
    const float* b2  = (const float*)d_in[14];
    float* out = (float*)d_out;

    float *f, *x, *el, *er, *elmax;
    int *srcs, *deg, *rowptr, *cursor;
    cudaGetSymbolAddress((void**)&f,      g_f);
    cudaGetSymbolAddress((void**)&x,      g_x);
    cudaGetSymbolAddress((void**)&el,     g_el);
    cudaGetSymbolAddress((void**)&er,     g_er);
    cudaGetSymbolAddress((void**)&elmax,  g_elmax);
    cudaGetSymbolAddress((void**)&srcs,   g_srcs);
    cudaGetSymbolAddress((void**)&deg,    g_deg);
    cudaGetSymbolAddress((void**)&rowptr, g_rowptr);
    cudaGetSymbolAddress((void**)&cursor, g_cursor);

    float* emax0 = elmax;       // buf 0: layers 0 and 2
    float* emax1 = elmax + 4;   // buf 1: layer 1

    const int lin_blocks = (NN + 127) / 128;           // 391
    const int hist_blocks = (NE / 4 + 255) / 256;      // 782
    const int nd_blocks = (NN * 16 + 255) / 256;       // 2 nodes/warp

    // init: deg = 0, both elmax bufs = 0xFFFFFFFF (identity for atomicMaxF)
    cudaMemsetAsync(deg, 0, NN * sizeof(int));
    cudaMemsetAsync(elmax, 0xFF, 8 * sizeof(float));

    // layer-0 GEMM fused with degree histogram (independent)
    linear_hist_kernel<128, 4><<<lin_blocks + hist_blocks, 256>>>(
        h, W0, al0, ar0, f, el, er, emax0, NN, lin_blocks, dst, deg, NE);
    scan_kernel<<<1, 1024>>>(deg, rowptr, cursor, NN);
    scatter_kernel<<<hist_blocks, 256>>>(src, dst, cursor, srcs, NE);

    gat_node_kernel<4><<<nd_blocks, 256>>>(rowptr, srcs, f, el, er, emax0, b0, x, NN, 1, nullptr);

    // layer 1 (its gat_node resets buf0 for layer 2)
    linear_kernel<64, 4><<<lin_blocks, 256>>>(x, W1, al1, ar1, f, el, er, emax1, NN);
    gat_node_kernel<4><<<nd_blocks, 256>>>(rowptr, srcs, f, el, er, emax1, b1, x, NN, 1, emax0);

    // layer 2
    linear_kernel<64, 1><<<lin_blocks, 256>>>(x, W2, al2, ar2, f, el, er, emax0, NN);
    gat_node_kernel<1><<<nd_blocks, 256>>>(rowptr, srcs, f, el, er, emax0, b2, out, NN, 0, nullptr);
}